// round 13
// baseline (speedup 1.0000x reference)
#include <cuda_runtime.h>
#include <math.h>
#include <stdint.h>

#define NLVL 16
#define TSIZE (1u << 19)
#define TMASK (TSIZE - 1u)
#define HPRIME 2654435761u

#define NPTS_MAX 2097152
#define NBUCK 65536

__device__ uint32_t g_hist[NBUCK];
__device__ uint32_t g_cursor[NBUCK];
__device__ uint32_t g_bsum[256];
__device__ uint32_t g_perm[NPTS_MAX];

// fragment-packed tf32-rounded weights: L1 40x64 (5kt x 8nt), L2 64x64 (8x8), L3 64x8 (8x1)
#define B1_F 0
#define B2_F 2560
#define B3_F 6656
#define WPACKF 7168
__device__ float g_wfrag[WPACKF];

#define SA_STRIDE 68
#define SA_BASE 7168
#define PAIR_FLOATS (64 * SA_STRIDE)               // 4352
#define PID_BASE (SA_BASE + 4 * PAIR_FLOATS)       // 24576
#define SMEM_FLOATS (PID_BASE + 256)               // 24832
#define SMEM_BYTES (SMEM_FLOATS * 4)

struct LevelParams {
    float resf[NLVL];
    int   res1[NLVL];
    int   dense[NLVL];
};

// ---------------- Morton helpers ----------------
__device__ __forceinline__ uint32_t part1by1(uint32_t x) {
    x &= 0xFFu;
    x = (x | (x << 4)) & 0x0F0Fu;
    x = (x | (x << 2)) & 0x3333u;
    x = (x | (x << 1)) & 0x5555u;
    return x;
}
__device__ __forceinline__ uint32_t bucket_code(float px, float py) {
    int bx = (int)(px * 256.0f); bx = bx < 0 ? 0 : (bx > 255 ? 255 : bx);
    int by = (int)(py * 256.0f); by = by < 0 ? 0 : (by > 255 ? 255 : by);
    return part1by1((uint32_t)bx) | (part1by1((uint32_t)by) << 1);
}

// ---------------- fused setup: zero hist + pack tf32 weights ----------------
__global__ void setup_kernel(const float* __restrict__ w1,
                             const float* __restrict__ w2,
                             const float* __restrict__ w3) {
    int b = blockIdx.x;
    int t = threadIdx.x;
    if (b < 256) {
        g_hist[b * 256 + t] = 0u;
        return;
    }
    int e = (b - 256) * 256 + t;
    if (e >= WPACKF) return;
    int base, NT, rel;
    const float* W; int ncols; int kmax;
    if (e < B2_F)      { base = B1_F; NT = 8; rel = e - B1_F; W = w1; ncols = 64; kmax = 34; }
    else if (e < B3_F) { base = B2_F; NT = 8; rel = e - B2_F; W = w2; ncols = 64; kmax = 64; }
    else               { base = B3_F; NT = 1; rel = e - B3_F; W = w3; ncols = 3;  kmax = 64; }
    int tile = rel >> 6;
    int r    = rel & 63;
    int lane = r >> 1, sel = r & 1;
    int kt = tile / NT, nt = tile % NT;
    int k = kt * 8 + (lane & 3) + sel * 4;
    int n = nt * 8 + (lane >> 2);
    float v = 0.0f;
    if (k < kmax && n < ncols) v = W[k * ncols + n];
    uint32_t hb;
    asm("cvt.rna.tf32.f32 %0, %1;" : "=r"(hb) : "f"(v));
    g_wfrag[e] = __uint_as_float(hb);
}

// ---------------- hist (4 pts per thread) ----------------
__global__ void hist_kernel(const float4* __restrict__ xin4, int npts) {
    int t = blockIdx.x * 256 + threadIdx.x;
    int i0 = t * 4;
    if (i0 >= npts) return;
    float4 a = __ldg(xin4 + t * 2);
    float4 b = __ldg(xin4 + t * 2 + 1);
    atomicAdd(&g_hist[bucket_code(a.x, a.y)], 1u);
    if (i0 + 1 < npts) atomicAdd(&g_hist[bucket_code(a.z, a.w)], 1u);
    if (i0 + 2 < npts) atomicAdd(&g_hist[bucket_code(b.x, b.y)], 1u);
    if (i0 + 3 < npts) atomicAdd(&g_hist[bucket_code(b.z, b.w)], 1u);
}

// ---------------- 2-stage scan: local-exclusive in cursor + block offsets in bsum ----
__global__ __launch_bounds__(256) void scanA_kernel() {
    __shared__ uint32_t sh[256];
    const int b = blockIdx.x, t = threadIdx.x;
    uint32_t v = g_hist[b * 256 + t];
    sh[t] = v;
    __syncthreads();
    for (int d = 1; d < 256; d <<= 1) {
        uint32_t u = (t >= d) ? sh[t - d] : 0u;
        __syncthreads();
        sh[t] += u;
        __syncthreads();
    }
    g_cursor[b * 256 + t] = sh[t] - v;          // local exclusive
    if (t == 255) g_bsum[b] = sh[255];          // block total
}
__global__ __launch_bounds__(256) void scanB_kernel() {
    __shared__ uint32_t sh[256];
    const int t = threadIdx.x;
    uint32_t v = g_bsum[t];
    sh[t] = v;
    __syncthreads();
    for (int d = 1; d < 256; d <<= 1) {
        uint32_t u = (t >= d) ? sh[t - d] : 0u;
        __syncthreads();
        sh[t] += u;
        __syncthreads();
    }
    g_bsum[t] = sh[t] - v;                      // exclusive block offset
}

// ---------------- scatter (4 pts per thread; adds block offset at use) ----------------
__device__ __forceinline__ void scat1(float px, float py, int idx) {
    uint32_t c = bucket_code(px, py);
    uint32_t s = atomicAdd(&g_cursor[c], 1u) + g_bsum[c >> 8];
    g_perm[s] = (uint32_t)idx;
}
__global__ void scatter_kernel(const float4* __restrict__ xin4, int npts) {
    int t = blockIdx.x * 256 + threadIdx.x;
    int i0 = t * 4;
    if (i0 >= npts) return;
    float4 a = __ldg(xin4 + t * 2);
    float4 b = __ldg(xin4 + t * 2 + 1);
    scat1(a.x, a.y, i0);
    if (i0 + 1 < npts) scat1(a.z, a.w, i0 + 1);
    if (i0 + 2 < npts) scat1(b.x, b.y, i0 + 2);
    if (i0 + 3 < npts) scat1(b.z, b.w, i0 + 3);
}

// ---------------- mma helpers ----------------
__device__ __forceinline__ void cvt_hilo(float v, uint32_t& h, uint32_t& l) {
    uint32_t hb;
    asm("cvt.rna.tf32.f32 %0, %1;" : "=r"(hb) : "f"(v));
    h = hb;
    l = __float_as_uint(v - __uint_as_float(hb));
}
__device__ __forceinline__ void mma8(float c[4], const uint32_t a[4], const uint32_t b[2]) {
    asm volatile("mma.sync.aligned.m16n8k8.row.col.f32.tf32.tf32.f32 "
        "{%0,%1,%2,%3}, {%4,%5,%6,%7}, {%8,%9}, {%0,%1,%2,%3};"
        : "+f"(c[0]), "+f"(c[1]), "+f"(c[2]), "+f"(c[3])
        : "r"(a[0]), "r"(a[1]), "r"(a[2]), "r"(a[3]), "r"(b[0]), "r"(b[1]));
}
__device__ __forceinline__ void pair_bar(int pair) {
    asm volatile("bar.sync %0, 64;" :: "r"(pair + 1) : "memory");
}

// pair-shared mma: this warp computes 4 nt-tiles (offset nto) over 64 rows (mt=0..3)
template<int KT>
__device__ __forceinline__ void mma_layer_pair(const float* __restrict__ sB,
                                               const float* __restrict__ sA,
                                               float C[4][4][4], int lane, int nto) {
    const int g = lane >> 2, c = lane & 3;
#pragma unroll
    for (int mt = 0; mt < 4; mt++)
#pragma unroll
        for (int nt = 0; nt < 4; nt++)
#pragma unroll
            for (int r = 0; r < 4; r++) C[mt][nt][r] = 0.0f;

#pragma unroll 1
    for (int kt = 0; kt < KT; kt++) {
        uint32_t Bh[4][2];
#pragma unroll
        for (int nt = 0; nt < 4; nt++) {
            float2 bv = *(const float2*)(sB + (kt * 8 + nto + nt) * 64 + lane * 2);
            Bh[nt][0] = __float_as_uint(bv.x);
            Bh[nt][1] = __float_as_uint(bv.y);
        }
#pragma unroll
        for (int mt = 0; mt < 4; mt++) {
            const float* ar = sA + (mt * 16 + g) * SA_STRIDE + kt * 8;
            uint32_t Ah[4], Al[4];
            cvt_hilo(ar[c],                     Ah[0], Al[0]);
            cvt_hilo(ar[8 * SA_STRIDE + c],     Ah[1], Al[1]);
            cvt_hilo(ar[c + 4],                 Ah[2], Al[2]);
            cvt_hilo(ar[8 * SA_STRIDE + c + 4], Ah[3], Al[3]);
#pragma unroll
            for (int nt = 0; nt < 4; nt++) {
                mma8(C[mt][nt], Ah, Bh[nt]);
                mma8(C[mt][nt], Al, Bh[nt]);
            }
        }
    }
}

// store relu'd C into pair A tile: this warp owns cols [nto*8, nto*8+32)
__device__ __forceinline__ void store_relu_pair(float* __restrict__ sA,
                                                float C[4][4][4], int lane, int nto) {
    const int g = lane >> 2, c = lane & 3;
#pragma unroll
    for (int mt = 0; mt < 4; mt++)
#pragma unroll
        for (int nt = 0; nt < 4; nt++) {
            float* p = sA + (mt * 16 + g) * SA_STRIDE + (nto + nt) * 8 + 2 * c;
            *(float2*)p = make_float2(fmaxf(C[mt][nt][0], 0.f), fmaxf(C[mt][nt][1], 0.f));
            *(float2*)(p + 8 * SA_STRIDE) =
                make_float2(fmaxf(C[mt][nt][2], 0.f), fmaxf(C[mt][nt][3], 0.f));
        }
}

// ---------------- main fused kernel: warp-pairs share 64-row A tiles ----------------
__global__ __launch_bounds__(256, 2)
void videohash_kernel(const float2* __restrict__ xin,
                      const float2* __restrict__ tables,
                      float* __restrict__ out,
                      int npts, LevelParams lp)
{
    extern __shared__ float smf[];
    int* s_pid = (int*)(smf + PID_BASE);

    const int tid  = threadIdx.x;
    const int warp = tid >> 5;
    const int lane = tid & 31;
    const int pair = warp >> 1;
    const int half = warp & 1;          // 0 or 1 within pair
    const int nto  = half * 4;          // nt offset for this warp
    float* sA = smf + SA_BASE + pair * PAIR_FLOATS;

    // stage weights to SMEM (coalesced, 7 float4 per thread)
    {
        const float4* src = (const float4*)g_wfrag;
        float4* dst = (float4*)smf;
#pragma unroll
        for (int i = 0; i < 7; i++) dst[i * 256 + tid] = src[i * 256 + tid];
    }

    int slot = blockIdx.x * 256 + tid;
    if (slot >= npts) slot = npts - 1;
    const int pid = (int)g_perm[slot];
    s_pid[tid] = pid;
    const float2 p = __ldg(xin + pid);

    // -------- encode --------
    float enc[36];
    enc[0] = p.x; enc[1] = p.y; enc[34] = 0.f; enc[35] = 0.f;
#pragma unroll
    for (int l = 0; l < NLVL; l++) {
        const float rf = lp.resf[l];
        float px = p.x * rf, py = p.y * rf;
        float fx = floorf(px), fy = floorf(py);
        float wx = px - fx, wy = py - fy;
        unsigned X = (unsigned)fx, Y = (unsigned)fy;
        const float2* tab = tables + (size_t)l * TSIZE;
        unsigned i00, i10, i01, i11;
        if (lp.dense[l]) {
            unsigned r1 = (unsigned)lp.res1[l];
            unsigned b = X + Y * r1;
            i00 = b; i10 = b + 1u; i01 = b + r1; i11 = b + r1 + 1u;
        } else {
            unsigned hy = Y * HPRIME, hy1 = (Y + 1u) * HPRIME;
            i00 = (X ^ hy)  & TMASK; i10 = ((X + 1u) ^ hy)  & TMASK;
            i01 = (X ^ hy1) & TMASK; i11 = ((X + 1u) ^ hy1) & TMASK;
        }
        float2 f00 = __ldg(tab + i00), f10 = __ldg(tab + i10);
        float2 f01 = __ldg(tab + i01), f11 = __ldg(tab + i11);
        float w00 = (1.f - wx) * (1.f - wy), w10 = wx * (1.f - wy);
        float w01 = (1.f - wx) * wy,         w11 = wx * wy;
        enc[2 + 2 * l]     = f00.x * w00 + f10.x * w10 + f01.x * w01 + f11.x * w11;
        enc[2 + 2 * l + 1] = f00.y * w00 + f10.y * w10 + f01.y * w01 + f11.y * w11;
    }

    // stage enc to pair A tile, row = half*32 + lane
    {
        float* row = sA + (half * 32 + lane) * SA_STRIDE;
#pragma unroll
        for (int j = 0; j < 9; j++)
            *(float4*)(row + 4 * j) =
                make_float4(enc[4 * j], enc[4 * j + 1], enc[4 * j + 2], enc[4 * j + 3]);
        *(float4*)(row + 36) = make_float4(0.f, 0.f, 0.f, 0.f);
    }
    __syncthreads();   // weights + all A tiles staged

    // -------- layer 1: K=40, warp computes nt[nto..nto+4) over 64 rows --------
    {
        float C[4][4][4];
        mma_layer_pair<5>(smf + B1_F, sA, C, lane, nto);
        pair_bar(pair);                 // A reads done in both warps
        store_relu_pair(sA, C, lane, nto);
        pair_bar(pair);                 // new A tile complete
    }
    // -------- layer 2: K=64 --------
    {
        float C[4][4][4];
        mma_layer_pair<8>(smf + B2_F, sA, C, lane, nto);
        pair_bar(pair);
        store_relu_pair(sA, C, lane, nto);
        pair_bar(pair);
    }
    // -------- layer 3: N=8 (3 valid), rows split between the pair (mt=2 each) --------
    {
        const int g = lane >> 2, c = lane & 3;
        float C[2][4];
#pragma unroll
        for (int mt = 0; mt < 2; mt++)
#pragma unroll
            for (int r = 0; r < 4; r++) C[mt][r] = 0.0f;
        const float* sB = smf + B3_F;
#pragma unroll 1
        for (int kt = 0; kt < 8; kt++) {
            float2 bv = *(const float2*)(sB + kt * 64 + lane * 2);
            uint32_t Bh[2] = { __float_as_uint(bv.x), __float_as_uint(bv.y) };
#pragma unroll
            for (int mt = 0; mt < 2; mt++) {
                const float* ar = sA + ((half * 2 + mt) * 16 + g) * SA_STRIDE + kt * 8;
                uint32_t Ah[4], Al[4];
                cvt_hilo(ar[c],                     Ah[0], Al[0]);
                cvt_hilo(ar[8 * SA_STRIDE + c],     Ah[1], Al[1]);
                cvt_hilo(ar[c + 4],                 Ah[2], Al[2]);
                cvt_hilo(ar[8 * SA_STRIDE + c + 4], Ah[3], Al[3]);
                mma8(C[mt], Ah, Bh);
                mma8(C[mt], Al, Bh);
            }
        }

#pragma unroll
        for (int mt = 0; mt < 2; mt++) {
            int r0 = (half * 2 + mt) * 16 + g;
            int pa = s_pid[pair * 64 + r0];
            int pb = s_pid[pair * 64 + r0 + 8];
            if (c == 0) {
                out[pa * 3 + 0] = C[mt][0];
                out[pa * 3 + 1] = C[mt][1];
                out[pb * 3 + 0] = C[mt][2];
                out[pb * 3 + 1] = C[mt][3];
            } else if (c == 1) {
                out[pa * 3 + 2] = C[mt][0];
                out[pb * 3 + 2] = C[mt][2];
            }
        }
    }
}

extern "C" void kernel_launch(void* const* d_in, const int* in_sizes, int n_in,
                              void* d_out, int out_size)
{
    const float* x      = (const float*)d_in[0];
    const float* tables = (const float*)d_in[1];
    const float* w1     = (const float*)d_in[2];
    const float* w2     = (const float*)d_in[3];
    const float* w3     = (const float*)d_in[4];

    const int npts = in_sizes[0] / 2;

    LevelParams lp;
    for (int l = 0; l < NLVL; l++) {
        int res = (int)floor(16.0 * pow(1.3819, (double)l));
        lp.resf[l]  = (float)res;
        lp.res1[l]  = res + 1;
        long long dsz = (long long)(res + 1) * (long long)(res + 1);
        lp.dense[l] = (dsz <= (long long)TSIZE) ? 1 : 0;
    }

    cudaFuncSetAttribute(videohash_kernel,
                         cudaFuncAttributeMaxDynamicSharedMemorySize, SMEM_BYTES);

    const int nq = (npts + 3) / 4;
    const int nbq = (nq + 255) / 256;

    setup_kernel<<<256 + (WPACKF + 255) / 256, 256>>>(w1, w2, w3);
    hist_kernel<<<nbq, 256>>>((const float4*)x, npts);
    scanA_kernel<<<256, 256>>>();
    scanB_kernel<<<1, 256>>>();
    scatter_kernel<<<nbq, 256>>>((const float4*)x, npts);

    int blocks = (npts + 255) / 256;
    videohash_kernel<<<blocks, 256, SMEM_BYTES>>>((const float2*)x, (const float2*)tables,
                                                  (float*)d_out, npts, lp);
}

// round 15
// speedup vs baseline: 1.2089x; 1.2089x over previous
#include <cuda_runtime.h>
#include <math.h>
#include <stdint.h>

#define NLVL 16
#define TSIZE (1u << 19)
#define TMASK (TSIZE - 1u)
#define HPRIME 2654435761u

#define NPTS_MAX 2097152
#define NBUCK 65536

__device__ uint32_t g_hist[NBUCK];
__device__ uint32_t g_cursor[NBUCK];
__device__ uint32_t g_bsum[256];
__device__ uint32_t g_perm[NPTS_MAX];
__device__ uint32_t g_pack[NPTS_MAX];   // (bucket<<16) | rank-within-bucket

// fragment-packed tf32-rounded weights: L1 40x64 (5kt x 8nt), L2 64x64 (8x8), L3 64x8 (8x1)
#define B1_F 0
#define B2_F 2560
#define B3_F 6656
#define WPACKF 7168
__device__ float g_wfrag[WPACKF];

#define SA_STRIDE 68
#define SA_BASE 7168
#define NWARP 8
#define SMEM_FLOATS (SA_BASE + NWARP * 32 * SA_STRIDE)   // 24576
#define SMEM_BYTES (SMEM_FLOATS * 4)

struct LevelParams {
    float resf[NLVL];
    int   res1[NLVL];
    int   dense[NLVL];
};

// ---------------- Morton helpers ----------------
__device__ __forceinline__ uint32_t part1by1(uint32_t x) {
    x &= 0xFFu;
    x = (x | (x << 4)) & 0x0F0Fu;
    x = (x | (x << 2)) & 0x3333u;
    x = (x | (x << 1)) & 0x5555u;
    return x;
}
__device__ __forceinline__ uint32_t bucket_code(float px, float py) {
    int bx = (int)(px * 256.0f); bx = bx < 0 ? 0 : (bx > 255 ? 255 : bx);
    int by = (int)(py * 256.0f); by = by < 0 ? 0 : (by > 255 ? 255 : by);
    return part1by1((uint32_t)bx) | (part1by1((uint32_t)by) << 1);
}

// ---------------- fused setup: zero hist + pack tf32 weights ----------------
__global__ void setup_kernel(const float* __restrict__ w1,
                             const float* __restrict__ w2,
                             const float* __restrict__ w3) {
    int b = blockIdx.x;
    int t = threadIdx.x;
    if (b < 256) {
        g_hist[b * 256 + t] = 0u;
        return;
    }
    int e = (b - 256) * 256 + t;
    if (e >= WPACKF) return;
    int base, NT, rel;
    const float* W; int ncols; int kmax;
    if (e < B2_F)      { base = B1_F; NT = 8; rel = e - B1_F; W = w1; ncols = 64; kmax = 34; }
    else if (e < B3_F) { base = B2_F; NT = 8; rel = e - B2_F; W = w2; ncols = 64; kmax = 64; }
    else               { base = B3_F; NT = 1; rel = e - B3_F; W = w3; ncols = 3;  kmax = 64; }
    int tile = rel >> 6;
    int r    = rel & 63;
    int lane = r >> 1, sel = r & 1;
    int kt = tile / NT, nt = tile % NT;
    int k = kt * 8 + (lane & 3) + sel * 4;
    int n = nt * 8 + (lane >> 2);
    float v = 0.0f;
    if (k < kmax && n < ncols) v = W[k * ncols + n];
    uint32_t hb;
    asm("cvt.rna.tf32.f32 %0, %1;" : "=r"(hb) : "f"(v));
    g_wfrag[e] = __uint_as_float(hb);
}

// ---------------- hist: counts + per-point (bucket, rank) pack ----------------
__device__ __forceinline__ uint32_t hist1(float px, float py) {
    uint32_t c = bucket_code(px, py);
    uint32_t r = atomicAdd(&g_hist[c], 1u);
    return (c << 16) | (r & 0xFFFFu);
}
__global__ void hist_kernel(const float4* __restrict__ xin4, int npts) {
    int t = blockIdx.x * 256 + threadIdx.x;
    int i0 = t * 4;
    if (i0 >= npts) return;
    float4 a = __ldg(xin4 + t * 2);
    float4 b = __ldg(xin4 + t * 2 + 1);
    g_pack[i0] = hist1(a.x, a.y);
    if (i0 + 1 < npts) g_pack[i0 + 1] = hist1(a.z, a.w);
    if (i0 + 2 < npts) g_pack[i0 + 2] = hist1(b.x, b.y);
    if (i0 + 3 < npts) g_pack[i0 + 3] = hist1(b.z, b.w);
}

// ---------------- 2-stage scan: local-exclusive in cursor + block offsets in bsum ----
__global__ __launch_bounds__(256) void scanA_kernel() {
    __shared__ uint32_t sh[256];
    const int b = blockIdx.x, t = threadIdx.x;
    uint32_t v = g_hist[b * 256 + t];
    sh[t] = v;
    __syncthreads();
    for (int d = 1; d < 256; d <<= 1) {
        uint32_t u = (t >= d) ? sh[t - d] : 0u;
        __syncthreads();
        sh[t] += u;
        __syncthreads();
    }
    g_cursor[b * 256 + t] = sh[t] - v;          // local exclusive
    if (t == 255) g_bsum[b] = sh[255];          // block total
}
__global__ __launch_bounds__(256) void scanB_kernel() {
    __shared__ uint32_t sh[256];
    const int t = threadIdx.x;
    uint32_t v = g_bsum[t];
    sh[t] = v;
    __syncthreads();
    for (int d = 1; d < 256; d <<= 1) {
        uint32_t u = (t >= d) ? sh[t - d] : 0u;
        __syncthreads();
        sh[t] += u;
        __syncthreads();
    }
    g_bsum[t] = sh[t] - v;                      // exclusive block offset
}

// ---------------- scatter: atomic-free, rank-based ----------------
__global__ void scatter_kernel(int npts) {
    int t = blockIdx.x * 256 + threadIdx.x;
    int i0 = t * 4;
    if (i0 >= npts) return;
    uint4 pk = *((const uint4*)g_pack + t);
#pragma unroll
    for (int j = 0; j < 4; j++) {
        int idx = i0 + j;
        if (idx >= npts) break;
        uint32_t v = (j == 0) ? pk.x : (j == 1) ? pk.y : (j == 2) ? pk.z : pk.w;
        uint32_t c = v >> 16;
        uint32_t r = v & 0xFFFFu;
        uint32_t s = g_cursor[c] + g_bsum[c >> 8] + r;
        g_perm[s] = (uint32_t)idx;
    }
}

// ---------------- mma helpers ----------------
__device__ __forceinline__ void cvt_hilo(float v, uint32_t& h, uint32_t& l) {
    uint32_t hb;
    asm("cvt.rna.tf32.f32 %0, %1;" : "=r"(hb) : "f"(v));
    h = hb;
    l = __float_as_uint(v - __uint_as_float(hb));
}
__device__ __forceinline__ void mma8(float c[4], const uint32_t a[4], const uint32_t b[2]) {
    asm volatile("mma.sync.aligned.m16n8k8.row.col.f32.tf32.tf32.f32 "
        "{%0,%1,%2,%3}, {%4,%5,%6,%7}, {%8,%9}, {%0,%1,%2,%3};"
        : "+f"(c[0]), "+f"(c[1]), "+f"(c[2]), "+f"(c[3])
        : "r"(a[0]), "r"(a[1]), "r"(a[2]), "r"(a[3]), "r"(b[0]), "r"(b[1]));
}

template<int KT, int NT>
__device__ __forceinline__ void mma_layer(const float* __restrict__ sB,
                                          const float* __restrict__ sA,
                                          float C[2][NT][4], int lane) {
    const int g = lane >> 2, c = lane & 3;
#pragma unroll
    for (int mt = 0; mt < 2; mt++)
#pragma unroll
        for (int nt = 0; nt < NT; nt++)
#pragma unroll
            for (int r = 0; r < 4; r++) C[mt][nt][r] = 0.0f;

#pragma unroll 1
    for (int kt = 0; kt < KT; kt++) {
        uint32_t Bh[NT][2];
#pragma unroll
        for (int nt = 0; nt < NT; nt++) {
            float2 bv = *(const float2*)(sB + (kt * NT + nt) * 64 + lane * 2);
            Bh[nt][0] = __float_as_uint(bv.x);   // pre-rounded tf32
            Bh[nt][1] = __float_as_uint(bv.y);
        }
#pragma unroll
        for (int mt = 0; mt < 2; mt++) {
            const float* ar = sA + (mt * 16 + g) * SA_STRIDE + kt * 8;
            uint32_t Ah[4], Al[4];
            cvt_hilo(ar[c],                     Ah[0], Al[0]);
            cvt_hilo(ar[8 * SA_STRIDE + c],     Ah[1], Al[1]);
            cvt_hilo(ar[c + 4],                 Ah[2], Al[2]);
            cvt_hilo(ar[8 * SA_STRIDE + c + 4], Ah[3], Al[3]);
#pragma unroll
            for (int nt = 0; nt < NT; nt++) {
                mma8(C[mt][nt], Ah, Bh[nt]);
                mma8(C[mt][nt], Al, Bh[nt]);
            }
        }
    }
}

template<int NT>
__device__ __forceinline__ void store_relu(float* __restrict__ sA,
                                           float C[2][NT][4], int lane) {
    const int g = lane >> 2, c = lane & 3;
#pragma unroll
    for (int mt = 0; mt < 2; mt++)
#pragma unroll
        for (int nt = 0; nt < NT; nt++) {
            float* p = sA + (mt * 16 + g) * SA_STRIDE + nt * 8 + 2 * c;
            *(float2*)p = make_float2(fmaxf(C[mt][nt][0], 0.f), fmaxf(C[mt][nt][1], 0.f));
            *(float2*)(p + 8 * SA_STRIDE) =
                make_float2(fmaxf(C[mt][nt][2], 0.f), fmaxf(C[mt][nt][3], 0.f));
        }
}

// ---------------- main fused kernel (exact R12/R6 form) ----------------
__global__ __launch_bounds__(256, 2)
void videohash_kernel(const float2* __restrict__ xin,
                      const float2* __restrict__ tables,
                      float* __restrict__ out,
                      int npts, LevelParams lp)
{
    extern __shared__ float smf[];

    const int tid  = threadIdx.x;
    const int warp = tid >> 5;
    const int lane = tid & 31;
    float* sA = smf + SA_BASE + warp * (32 * SA_STRIDE);

    // stage weights to SMEM (coalesced, 7 float4 per thread)
    {
        const float4* src = (const float4*)g_wfrag;
        float4* dst = (float4*)smf;
#pragma unroll
        for (int i = 0; i < 7; i++) dst[i * 256 + tid] = src[i * 256 + tid];
    }

    int slot = blockIdx.x * 256 + tid;
    if (slot >= npts) slot = npts - 1;
    const int pid = (int)g_perm[slot];
    const float2 p = __ldg(xin + pid);

    // -------- encode --------
    float enc[36];
    enc[0] = p.x; enc[1] = p.y; enc[34] = 0.f; enc[35] = 0.f;
#pragma unroll
    for (int l = 0; l < NLVL; l++) {
        const float rf = lp.resf[l];
        float px = p.x * rf, py = p.y * rf;
        float fx = floorf(px), fy = floorf(py);
        float wx = px - fx, wy = py - fy;
        unsigned X = (unsigned)fx, Y = (unsigned)fy;
        const float2* tab = tables + (size_t)l * TSIZE;
        unsigned i00, i10, i01, i11;
        if (lp.dense[l]) {
            unsigned r1 = (unsigned)lp.res1[l];
            unsigned b = X + Y * r1;
            i00 = b; i10 = b + 1u; i01 = b + r1; i11 = b + r1 + 1u;
        } else {
            unsigned hy = Y * HPRIME, hy1 = (Y + 1u) * HPRIME;
            i00 = (X ^ hy)  & TMASK; i10 = ((X + 1u) ^ hy)  & TMASK;
            i01 = (X ^ hy1) & TMASK; i11 = ((X + 1u) ^ hy1) & TMASK;
        }
        float2 f00 = __ldg(tab + i00), f10 = __ldg(tab + i10);
        float2 f01 = __ldg(tab + i01), f11 = __ldg(tab + i11);
        float w00 = (1.f - wx) * (1.f - wy), w10 = wx * (1.f - wy);
        float w01 = (1.f - wx) * wy,         w11 = wx * wy;
        enc[2 + 2 * l]     = f00.x * w00 + f10.x * w10 + f01.x * w01 + f11.x * w11;
        enc[2 + 2 * l + 1] = f00.y * w00 + f10.y * w10 + f01.y * w01 + f11.y * w11;
    }

    // stage enc to A tile row = lane
    {
        float* row = sA + lane * SA_STRIDE;
#pragma unroll
        for (int j = 0; j < 9; j++)
            *(float4*)(row + 4 * j) =
                make_float4(enc[4 * j], enc[4 * j + 1], enc[4 * j + 2], enc[4 * j + 3]);
        *(float4*)(row + 36) = make_float4(0.f, 0.f, 0.f, 0.f);
    }
    __syncthreads();   // weights staged by whole block (A tiles are warp-private)

    // -------- layer 1: K=40, N=64 --------
    {
        float C[2][8][4];
        mma_layer<5, 8>(smf + B1_F, sA, C, lane);
        __syncwarp();
        store_relu<8>(sA, C, lane);
        __syncwarp();
    }
    // -------- layer 2: K=64, N=64 --------
    {
        float C[2][8][4];
        mma_layer<8, 8>(smf + B2_F, sA, C, lane);
        __syncwarp();
        store_relu<8>(sA, C, lane);
        __syncwarp();
    }
    // -------- layer 3: K=64, N=8 (3 valid) --------
    {
        float C[2][1][4];
        mma_layer<8, 1>(smf + B3_F, sA, C, lane);

        const int g = lane >> 2, c = lane & 3;
#pragma unroll
        for (int mt = 0; mt < 2; mt++) {
            int r0 = mt * 16 + g;
            int pa = __shfl_sync(0xFFFFFFFFu, pid, r0);
            int pb = __shfl_sync(0xFFFFFFFFu, pid, r0 + 8);
            if (c == 0) {
                out[pa * 3 + 0] = C[mt][0][0];
                out[pa * 3 + 1] = C[mt][0][1];
                out[pb * 3 + 0] = C[mt][0][2];
                out[pb * 3 + 1] = C[mt][0][3];
            } else if (c == 1) {
                out[pa * 3 + 2] = C[mt][0][0];
                out[pb * 3 + 2] = C[mt][0][2];
            }
        }
    }
}

extern "C" void kernel_launch(void* const* d_in, const int* in_sizes, int n_in,
                              void* d_out, int out_size)
{
    const float* x      = (const float*)d_in[0];
    const float* tables = (const float*)d_in[1];
    const float* w1     = (const float*)d_in[2];
    const float* w2     = (const float*)d_in[3];
    const float* w3     = (const float*)d_in[4];

    const int npts = in_sizes[0] / 2;

    LevelParams lp;
    for (int l = 0; l < NLVL; l++) {
        int res = (int)floor(16.0 * pow(1.3819, (double)l));
        lp.resf[l]  = (float)res;
        lp.res1[l]  = res + 1;
        long long dsz = (long long)(res + 1) * (long long)(res + 1);
        lp.dense[l] = (dsz <= (long long)TSIZE) ? 1 : 0;
    }

    cudaFuncSetAttribute(videohash_kernel,
                         cudaFuncAttributeMaxDynamicSharedMemorySize, SMEM_BYTES);

    const int nq = (npts + 3) / 4;
    const int nbq = (nq + 255) / 256;

    setup_kernel<<<256 + (WPACKF + 255) / 256, 256>>>(w1, w2, w3);
    hist_kernel<<<nbq, 256>>>((const float4*)x, npts);
    scanA_kernel<<<256, 256>>>();
    scanB_kernel<<<1, 256>>>();
    scatter_kernel<<<nbq, 256>>>(npts);

    int blocks = (npts + 255) / 256;
    videohash_kernel<<<blocks, 256, SMEM_BYTES>>>((const float2*)x, (const float2*)tables,
                                                  (float*)d_out, npts, lp);
}